// round 7
// baseline (speedup 1.0000x reference)
#include <cuda_runtime.h>

#define WARPS_PER_BLOCK 4
#define THREADS 128
#define GRID_BLOCKS 768
#define MAX_BLOCKS 1024
#define NSLOT 18   // u, ar, a, p, n, nri, am[4], pm[4], nm[4]

__device__ __align__(16) float g_w2[64];
__device__ float g_partials[MAX_BLOCKS * 3];
__device__ unsigned int g_count = 0;

__device__ __forceinline__ float wsum(float v) {
#pragma unroll
    for (int o = 16; o > 0; o >>= 1) v += __shfl_xor_sync(0xffffffffu, v, o);
    return v;
}

// -log(sigmoid(x)) = softplus(-x); fast + stable (tol is 1e-3)
__device__ __forceinline__ float nlsig(float x) {
    float z = -x;
    return fmaxf(z, 0.f) + __logf(1.f + __expf(-fabsf(z)));
}

__device__ __forceinline__ void cpa8(void* smem_dst, const void* gsrc) {
    unsigned s = (unsigned)__cvta_generic_to_shared(smem_dst);
    asm volatile("cp.async.ca.shared.global [%0], [%1], 8;" :: "r"(s), "l"(gsrc));
}
__device__ __forceinline__ void cpa_commit() {
    asm volatile("cp.async.commit_group;");
}
__device__ __forceinline__ void cpa_wait1() {
    asm volatile("cp.async.wait_group 1;");
}
__device__ __forceinline__ void cpa_wait0() {
    asm volatile("cp.async.wait_group 0;");
}

// w2[d] = sum_e att_w_W[d,e] * att_v_W[64+e]
__global__ void precompute_w2(const float* __restrict__ W, const float* __restrict__ vW) {
    const int d = threadIdx.x;
    const float4* Wr = (const float4*)(W + d * 64);
    const float4* vr = (const float4*)(vW + 64);
    float s = 0.f;
#pragma unroll
    for (int e = 0; e < 16; e++) {
        float4 w = __ldg(Wr + e);
        float4 v = __ldg(vr + e);
        s += w.x * v.x + w.y * v.y + w.z * v.z + w.w * v.w;
    }
    g_w2[d] = s;
}

struct Ids { int aid, pid, nid, uid, nrid, prid, nrel; };

__device__ __forceinline__ Ids load_ids(
    const int* __restrict__ u_id, const int* __restrict__ anchor_i_id,
    const int* __restrict__ pos_r_id, const int* __restrict__ pos_i_id,
    const int* __restrict__ neg_r_id, const int* __restrict__ neg_i_id,
    const int* __restrict__ neg_ri_id, int b)
{
    Ids s;
    s.aid  = __ldg(anchor_i_id + b);
    s.pid  = __ldg(pos_i_id + b);
    s.nid  = __ldg(neg_i_id + b);
    s.uid  = __ldg(u_id + b);
    s.nrid = __ldg(neg_ri_id + b);
    s.prid = __ldg(pos_r_id + b);
    s.nrel = __ldg(neg_r_id + b);
    return s;
}

// issue the 18 gathered rows of one sample into a smem stage (register-free in-flight)
__device__ __forceinline__ void stage_sample(
    float2 (*buf)[32], const Ids& id, int4 ma, int4 mp, int4 mn, int lane,
    const float* __restrict__ user_emb, const float* __restrict__ item_emb,
    const float* __restrict__ item_emb_r, const float* __restrict__ meta_emb)
{
    cpa8(&buf[0][lane], (const float2*)user_emb   + (size_t)id.uid  * 32 + lane);
    cpa8(&buf[1][lane], (const float2*)item_emb_r + (size_t)id.aid  * 32 + lane);
    cpa8(&buf[2][lane], (const float2*)item_emb   + (size_t)id.aid  * 32 + lane);
    cpa8(&buf[3][lane], (const float2*)item_emb   + (size_t)id.pid  * 32 + lane);
    cpa8(&buf[4][lane], (const float2*)item_emb   + (size_t)id.nid  * 32 + lane);
    cpa8(&buf[5][lane], (const float2*)item_emb   + (size_t)id.nrid * 32 + lane);
    const int mai[4] = {ma.x, ma.y, ma.z, ma.w};
    const int mpi[4] = {mp.x, mp.y, mp.z, mp.w};
    const int mni[4] = {mn.x, mn.y, mn.z, mn.w};
#pragma unroll
    for (int g = 0; g < 4; g++) {
        cpa8(&buf[6  + g][lane], (const float2*)meta_emb + (size_t)mai[g] * 32 + lane);
        cpa8(&buf[10 + g][lane], (const float2*)meta_emb + (size_t)mpi[g] * 32 + lane);
        cpa8(&buf[14 + g][lane], (const float2*)meta_emb + (size_t)mni[g] * 32 + lane);
    }
    cpa_commit();
}

__global__ void __launch_bounds__(THREADS) actr_main(
    const int* __restrict__ u_id, const int* __restrict__ anchor_i_id,
    const int* __restrict__ pos_r_id, const int* __restrict__ pos_i_id,
    const int* __restrict__ neg_r_id, const int* __restrict__ neg_i_id,
    const int* __restrict__ neg_ri_id, const int* __restrict__ item_meta,
    const float* __restrict__ user_emb, const float* __restrict__ rel_emb,
    const float* __restrict__ item_emb, const float* __restrict__ item_emb_r,
    const float* __restrict__ item_bias, const float* __restrict__ rel_bias,
    const float* __restrict__ meta_emb,
    float* __restrict__ out, int B, float invB)
{
    __shared__ float2 s_buf[WARPS_PER_BLOCK][2][NSLOT][32];

    const int lane = threadIdx.x & 31;
    const int wid = threadIdx.x >> 5;
    const int S = gridDim.x * WARPS_PER_BLOCK;

    // loop-invariant, warp-uniform data
    float2 w2 = __ldg((const float2*)g_w2 + lane);
    float2 re[3];
    float relb[3];
#pragma unroll
    for (int r = 0; r < 3; r++) {
        re[r] = __ldg((const float2*)rel_emb + r * 32 + lane);
        relb[r] = __ldg(rel_bias + r);
    }

    float accSeq = 0.f, accRel = 0.f, accItm = 0.f;

    const int b0 = blockIdx.x * WARPS_PER_BLOCK + wid;
    const int Bm1 = B - 1;

    // ---- prologue: ids + meta idx for samples 0 and 1, stage sample 0 into smem
    Ids idC = load_ids(u_id, anchor_i_id, pos_r_id, pos_i_id, neg_r_id, neg_i_id, neg_ri_id,
                       min(b0, Bm1));
    int4 maC = __ldg((const int4*)item_meta + idC.aid);
    int4 mpC = __ldg((const int4*)item_meta + idC.pid);
    int4 mnC = __ldg((const int4*)item_meta + idC.nid);
    Ids idN = load_ids(u_id, anchor_i_id, pos_r_id, pos_i_id, neg_r_id, neg_i_id, neg_ri_id,
                       min(b0 + S, Bm1));
    int4 maN = __ldg((const int4*)item_meta + idN.aid);
    int4 mpN = __ldg((const int4*)item_meta + idN.pid);
    int4 mnN = __ldg((const int4*)item_meta + idN.nid);
    stage_sample(s_buf[wid][0], idC, maC, mpC, mnC, lane, user_emb, item_emb, item_emb_r, meta_emb);
    float biasP = __ldg(item_bias + idC.pid);
    float biasN = __ldg(item_bias + idC.nid);
    float biasNR = __ldg(item_bias + idC.nrid);

    int st = 0;
    for (int b = b0; b < B; b += S) {
        // ---- issue prefetch of sample b+S into the other stage (register-free)
        stage_sample(s_buf[wid][st ^ 1], idN, maN, mpN, mnN, lane,
                     user_emb, item_emb, item_emb_r, meta_emb);
        float biasP_n  = __ldg(item_bias + idN.pid);
        float biasN_n  = __ldg(item_bias + idN.nid);
        float biasNR_n = __ldg(item_bias + idN.nrid);

        // ---- ids for sample b+2S (arrive during this iteration's compute)
        Ids idNN = load_ids(u_id, anchor_i_id, pos_r_id, pos_i_id, neg_r_id, neg_i_id, neg_ri_id,
                            min(b + 2 * S, Bm1));

        // ---- wait: all groups except the one just issued (i.e. current stage is ready)
        cpa_wait1();
        float2 (*buf)[32] = s_buf[wid][st];

        float2 u  = buf[0][lane];
        float2 ar = buf[1][lane];
        float2 a  = buf[2][lane];

        // ================= phase 1 =================
        // relation prediction: softmax_r( rel_bias[r] - ||u + a_r - rel_emb[r]||^2 )
        float rw[3];
#pragma unroll
        for (int r = 0; r < 3; r++) {
            float dx = u.x + ar.x - re[r].x;
            float dy = u.y + ar.y - re[r].y;
            rw[r] = relb[r] - wsum(dx * dx + dy * dy);
        }
        float mx = fmaxf(rw[0], fmaxf(rw[1], rw[2]));
        float ssum = 0.f;
#pragma unroll
        for (int r = 0; r < 3; r++) { rw[r] = __expf(rw[r] - mx); ssum += rw[r]; }
        float inv = __frcp_rn(ssum);
#pragma unroll
        for (int r = 0; r < 3; r++) rw[r] *= inv;

        // attention coef: softmax_c( i_plus[c] . w2 )
        float2 am[4];
#pragma unroll
        for (int g = 0; g < 4; g++) am[g] = buf[6 + g][lane];
        float cf[5];
        cf[0] = wsum(a.x * w2.x + a.y * w2.y);
#pragma unroll
        for (int g = 0; g < 4; g++)
            cf[1 + g] = wsum(am[g].x * w2.x + am[g].y * w2.y);
        mx = cf[0];
#pragma unroll
        for (int c = 1; c < 5; c++) mx = fmaxf(mx, cf[c]);
        ssum = 0.f;
#pragma unroll
        for (int c = 0; c < 5; c++) { cf[c] = __expf(cf[c] - mx); ssum += cf[c]; }
        inv = __frcp_rn(ssum);
#pragma unroll
        for (int c = 0; c < 5; c++) cf[c] *= inv;

        // ---- meta indices for b+2S (idNN has arrived)
        int4 maNN = __ldg((const int4*)item_meta + idNN.aid);
        int4 mpNN = __ldg((const int4*)item_meta + idNN.pid);
        int4 mnNN = __ldg((const int4*)item_meta + idNN.nid);

        // ================= phase 2 =================
        const float GAMMA = 0.5f;
        float2 rbar;
        rbar.x = GAMMA * (rw[0] * re[0].x + rw[1] * re[1].x + rw[2] * re[2].x) + (1.f - GAMMA) * u.x;
        rbar.y = GAMMA * (rw[0] * re[0].y + rw[1] * re[1].y + rw[2] * re[2].y) + (1.f - GAMMA) * u.y;

        float2 p   = buf[3][lane];
        float2 n   = buf[4][lane];
        float2 nri = buf[5][lane];

        // seq score difference in one reduction (srp & ||rue||^2 cancel)
        float diffpn;
        {
            float sdp = 0.f, dbxp = 0.f, dbyp = 0.f;
            float sdn = 0.f, dbxn = 0.f, dbyn = 0.f;
            float dx = a.x - p.x, dy = a.y - p.y;
            sdp += cf[0] * (dx * dx + dy * dy); dbxp += cf[0] * dx; dbyp += cf[0] * dy;
            dx = a.x - n.x; dy = a.y - n.y;
            sdn += cf[0] * (dx * dx + dy * dy); dbxn += cf[0] * dx; dbyn += cf[0] * dy;
#pragma unroll
            for (int g = 0; g < 4; g++) {
                float2 pm = buf[10 + g][lane];
                float2 nm = buf[14 + g][lane];
                dx = am[g].x - pm.x; dy = am[g].y - pm.y;
                sdp += cf[1 + g] * (dx * dx + dy * dy);
                dbxp += cf[1 + g] * dx; dbyp += cf[1 + g] * dy;
                dx = am[g].x - nm.x; dy = am[g].y - nm.y;
                sdn += cf[1 + g] * (dx * dx + dy * dy);
                dbxn += cf[1 + g] * dx; dbyn += cf[1 + g] * dy;
            }
            float sp = sdp + 2.f * (dbxp * rbar.x + dbyp * rbar.y);
            float sn = sdn + 2.f * (dbxn * rbar.x + dbyn * rbar.y);
            diffpn = wsum(sp - sn);
        }
        accSeq += nlsig((biasP - biasN) - diffpn);

        // relation loss
        float prs = (idC.prid == 0) ? rw[0] : ((idC.prid == 1) ? rw[1] : rw[2]);
        float nrs = (idC.nrel == 0) ? rw[0] : ((idC.nrel == 1) ? rw[1] : rw[2]);
        accRel += nlsig(prs - nrs);

        // item loss in one reduction
        float2 iir;
        iir.x = (idC.prid == 0) ? re[0].x : ((idC.prid == 1) ? re[1].x : re[2].x);
        iir.y = (idC.prid == 0) ? re[0].y : ((idC.prid == 1) ? re[1].y : re[2].y);
        float px = a.x + iir.x - p.x,   py = a.y + iir.y - p.y;
        float qx = a.x + iir.x - nri.x, qy = a.y + iir.y - nri.y;
        float di = wsum((px * px + py * py) - (qx * qx + qy * qy));
        accItm += nlsig((biasP - biasNR) - di);

        // ---- rotate
        idC = idN; idN = idNN;
        maN = maNN; mpN = mpNN; mnN = mnNN;
        biasP = biasP_n; biasN = biasN_n; biasNR = biasNR_n;
        st ^= 1;
    }
    cpa_wait0();  // drain outstanding prefetches before smem reuse / exit

    // ---- deterministic block-level partial sum
    __shared__ float sh[WARPS_PER_BLOCK][3];
    __shared__ bool is_last;
    if (lane == 0) { sh[wid][0] = accSeq; sh[wid][1] = accRel; sh[wid][2] = accItm; }
    __syncthreads();
    if (threadIdx.x == 0) {
        float s0 = 0.f, s1 = 0.f, s2 = 0.f;
#pragma unroll
        for (int w = 0; w < WARPS_PER_BLOCK; w++) {
            s0 += sh[w][0]; s1 += sh[w][1]; s2 += sh[w][2];
        }
        g_partials[blockIdx.x * 3 + 0] = s0;
        g_partials[blockIdx.x * 3 + 1] = s1;
        g_partials[blockIdx.x * 3 + 2] = s2;
        __threadfence();
        unsigned int old = atomicAdd(&g_count, 1u);
        is_last = (old == gridDim.x - 1);
    }
    __syncthreads();

    // ---- last arriving block does the final (fixed-order, deterministic) reduce
    if (is_last) {
        const int nblocks = gridDim.x;
        __shared__ float shf[3];
        if (wid < 3) {
            float s = 0.f;
            for (int i = lane; i < nblocks; i += 32) s += g_partials[i * 3 + wid];
            s = wsum(s) * invB;
            if (lane == 0) shf[wid] = s;
        }
        __syncthreads();
        if (threadIdx.x == 0) {
            float seq = shf[0], rel = shf[1], itm = shf[2];
            out[0] = seq + rel + itm;   // loss (ALPHA=BETA=1)
            out[1] = rel;               // relation_loss
            out[2] = seq;               // seq_loss
            out[3] = itm;               // item_loss
            g_count = 0;                // reset for next graph replay
        }
    }
}

extern "C" void kernel_launch(void* const* d_in, const int* in_sizes, int n_in,
                              void* d_out, int out_size) {
    const int*   u_id       = (const int*)d_in[0];
    const int*   anchor_i   = (const int*)d_in[1];
    const int*   pos_r      = (const int*)d_in[2];
    const int*   pos_i      = (const int*)d_in[3];
    const int*   neg_r      = (const int*)d_in[4];
    const int*   neg_i      = (const int*)d_in[5];
    const int*   neg_ri     = (const int*)d_in[6];
    const int*   item_meta  = (const int*)d_in[7];
    const float* user_emb   = (const float*)d_in[8];
    const float* rel_emb    = (const float*)d_in[9];
    const float* item_emb   = (const float*)d_in[10];
    const float* item_emb_r = (const float*)d_in[11];
    const float* item_bias  = (const float*)d_in[12];
    const float* rel_bias   = (const float*)d_in[13];
    const float* meta_emb   = (const float*)d_in[14];
    const float* att_w_W    = (const float*)d_in[15];
    const float* att_v_W    = (const float*)d_in[17];

    const int B = in_sizes[0];

    precompute_w2<<<1, 64>>>(att_w_W, att_v_W);
    actr_main<<<GRID_BLOCKS, THREADS>>>(u_id, anchor_i, pos_r, pos_i, neg_r, neg_i, neg_ri,
                                        item_meta, user_emb, rel_emb, item_emb, item_emb_r,
                                        item_bias, rel_bias, meta_emb,
                                        (float*)d_out, B, 1.0f / (float)B);
}

// round 8
// speedup vs baseline: 1.0903x; 1.0903x over previous
#include <cuda_runtime.h>

#define WARPS_PER_BLOCK 4
#define THREADS 128
#define GRID_BLOCKS 888
#define MAX_BLOCKS 1024

__device__ __align__(16) float g_w2[64];
__device__ float g_partials[MAX_BLOCKS * 3];
__device__ unsigned int g_count = 0;

__device__ __forceinline__ float wsum(float v) {
#pragma unroll
    for (int o = 16; o > 0; o >>= 1) v += __shfl_xor_sync(0xffffffffu, v, o);
    return v;
}

// -log(sigmoid(x)) = softplus(-x); fast + stable (tol is 1e-3)
__device__ __forceinline__ float nlsig(float x) {
    float z = -x;
    return fmaxf(z, 0.f) + __logf(1.f + __expf(-fabsf(z)));
}

// w2[d] = sum_e att_w_W[d,e] * att_v_W[64+e]
__global__ void precompute_w2(const float* __restrict__ W, const float* __restrict__ vW) {
    const int d = threadIdx.x;
    const float4* Wr = (const float4*)(W + d * 64);
    const float4* vr = (const float4*)(vW + 64);
    float s = 0.f;
#pragma unroll
    for (int e = 0; e < 16; e++) {
        float4 w = __ldg(Wr + e);
        float4 v = __ldg(vr + e);
        s += w.x * v.x + w.y * v.y + w.z * v.z + w.w * v.w;
    }
    g_w2[d] = s;
}

struct Ids { int aid, pid, nid, uid, nrid, prid, nrel; };

__device__ __forceinline__ Ids load_ids(
    const int* __restrict__ u_id, const int* __restrict__ anchor_i_id,
    const int* __restrict__ pos_r_id, const int* __restrict__ pos_i_id,
    const int* __restrict__ neg_r_id, const int* __restrict__ neg_i_id,
    const int* __restrict__ neg_ri_id, int b)
{
    Ids s;
    s.aid  = __ldg(anchor_i_id + b);
    s.pid  = __ldg(pos_i_id + b);
    s.nid  = __ldg(neg_i_id + b);
    s.uid  = __ldg(u_id + b);
    s.nrid = __ldg(neg_ri_id + b);
    s.prid = __ldg(pos_r_id + b);
    s.nrel = __ldg(neg_r_id + b);
    return s;
}

__global__ void __launch_bounds__(THREADS, 6) actr_main(
    const int* __restrict__ u_id, const int* __restrict__ anchor_i_id,
    const int* __restrict__ pos_r_id, const int* __restrict__ pos_i_id,
    const int* __restrict__ neg_r_id, const int* __restrict__ neg_i_id,
    const int* __restrict__ neg_ri_id, const int* __restrict__ item_meta,
    const float* __restrict__ user_emb, const float* __restrict__ rel_emb,
    const float* __restrict__ item_emb, const float* __restrict__ item_emb_r,
    const float* __restrict__ item_bias, const float* __restrict__ rel_bias,
    const float* __restrict__ meta_emb,
    float* __restrict__ out, int B, float invB)
{
    const int lane = threadIdx.x & 31;
    const int wid = threadIdx.x >> 5;
    const int S = gridDim.x * WARPS_PER_BLOCK;   // total warps = sample stride

    // ---- loop-invariant, warp-uniform data (hoisted; small reg footprint)
    float2 w2 = __ldg((const float2*)g_w2 + lane);
    float2 re[3];
#pragma unroll
    for (int r = 0; r < 3; r++)
        re[r] = __ldg((const float2*)rel_emb + r * 32 + lane);

    float accSeq = 0.f, accRel = 0.f, accItm = 0.f;

    int b = blockIdx.x * WARPS_PER_BLOCK + wid;

    // ---- pipeline prologue: ids + meta indices for first sample
    Ids cur;
    int4 cma, cmp, cmn;
    if (b < B) {
        cur = load_ids(u_id, anchor_i_id, pos_r_id, pos_i_id, neg_r_id, neg_i_id, neg_ri_id, b);
        cma = __ldg((const int4*)item_meta + cur.aid);
        cmp = __ldg((const int4*)item_meta + cur.pid);
        cmn = __ldg((const int4*)item_meta + cur.nid);
    }

    while (b < B) {
        const int nb = b + S;

        // ---- issue ALL embedding gathers for current sample (indices already resolved)
        float2 u   = __ldg((const float2*)user_emb   + (size_t)cur.uid  * 32 + lane);
        float2 ar  = __ldg((const float2*)item_emb_r + (size_t)cur.aid  * 32 + lane);
        float2 a   = __ldg((const float2*)item_emb   + (size_t)cur.aid  * 32 + lane);
        float2 p   = __ldg((const float2*)item_emb   + (size_t)cur.pid  * 32 + lane);
        float2 n   = __ldg((const float2*)item_emb   + (size_t)cur.nid  * 32 + lane);
        float2 nri = __ldg((const float2*)item_emb   + (size_t)cur.nrid * 32 + lane);

        int cmai[4] = {cma.x, cma.y, cma.z, cma.w};
        int cmpi[4] = {cmp.x, cmp.y, cmp.z, cmp.w};
        int cmni[4] = {cmn.x, cmn.y, cmn.z, cmn.w};
        float2 am[4], pm[4], nm[4];
#pragma unroll
        for (int g = 0; g < 4; g++) {
            am[g] = __ldg((const float2*)meta_emb + (size_t)cmai[g] * 32 + lane);
            pm[g] = __ldg((const float2*)meta_emb + (size_t)cmpi[g] * 32 + lane);
            nm[g] = __ldg((const float2*)meta_emb + (size_t)cmni[g] * 32 + lane);
        }

        // ---- prefetch NEXT sample's ids (arrive during compute below)
        Ids nxt;
        if (nb < B)
            nxt = load_ids(u_id, anchor_i_id, pos_r_id, pos_i_id, neg_r_id, neg_i_id, neg_ri_id, nb);

        // ---- relation prediction: softmax_r( rel_bias[r] - ||u + a_r - rel_emb[r]||^2 )
        float rw[3];
#pragma unroll
        for (int r = 0; r < 3; r++) {
            float dx = u.x + ar.x - re[r].x;
            float dy = u.y + ar.y - re[r].y;
            rw[r] = __ldg(rel_bias + r) - wsum(dx * dx + dy * dy);
        }
        float mx = fmaxf(rw[0], fmaxf(rw[1], rw[2]));
        float ssum = 0.f;
#pragma unroll
        for (int r = 0; r < 3; r++) { rw[r] = __expf(rw[r] - mx); ssum += rw[r]; }
        float inv = __frcp_rn(ssum);
#pragma unroll
        for (int r = 0; r < 3; r++) rw[r] *= inv;

        // ---- attention coef: softmax_c( i_plus[c] . w2 )
        float cf[5];
        cf[0] = wsum(a.x * w2.x + a.y * w2.y);
#pragma unroll
        for (int g = 0; g < 4; g++)
            cf[1 + g] = wsum(am[g].x * w2.x + am[g].y * w2.y);
        mx = cf[0];
#pragma unroll
        for (int c = 1; c < 5; c++) mx = fmaxf(mx, cf[c]);
        ssum = 0.f;
#pragma unroll
        for (int c = 0; c < 5; c++) { cf[c] = __expf(cf[c] - mx); ssum += cf[c]; }
        inv = __frcp_rn(ssum);
#pragma unroll
        for (int c = 0; c < 5; c++) cf[c] *= inv;

        // ---- prefetch NEXT sample's meta indices (nxt ids have arrived by now)
        int4 nma, nmp, nmn;
        if (nb < B) {
            nma = __ldg((const int4*)item_meta + nxt.aid);
            nmp = __ldg((const int4*)item_meta + nxt.pid);
            nmn = __ldg((const int4*)item_meta + nxt.nid);
        }

        // ---- rbar = sum_r rel[r]*rue[r]  (||rue||^2 term cancels in pos-neg diff)
        const float GAMMA = 0.5f;
        float2 rbar;
        rbar.x = GAMMA * (rw[0] * re[0].x + rw[1] * re[1].x + rw[2] * re[2].x) + (1.f - GAMMA) * u.x;
        rbar.y = GAMMA * (rw[0] * re[0].y + rw[1] * re[1].y + rw[2] * re[2].y) + (1.f - GAMMA) * u.y;

        // ---- seq score difference in one reduction
        float diffpn;
        {
            float sdp = 0.f, dbxp = 0.f, dbyp = 0.f;
            float sdn = 0.f, dbxn = 0.f, dbyn = 0.f;
            float dx = a.x - p.x, dy = a.y - p.y;
            sdp += cf[0] * (dx * dx + dy * dy); dbxp += cf[0] * dx; dbyp += cf[0] * dy;
            dx = a.x - n.x; dy = a.y - n.y;
            sdn += cf[0] * (dx * dx + dy * dy); dbxn += cf[0] * dx; dbyn += cf[0] * dy;
#pragma unroll
            for (int g = 0; g < 4; g++) {
                dx = am[g].x - pm[g].x; dy = am[g].y - pm[g].y;
                sdp += cf[1 + g] * (dx * dx + dy * dy);
                dbxp += cf[1 + g] * dx; dbyp += cf[1 + g] * dy;
                dx = am[g].x - nm[g].x; dy = am[g].y - nm[g].y;
                sdn += cf[1 + g] * (dx * dx + dy * dy);
                dbxn += cf[1 + g] * dx; dbyn += cf[1 + g] * dy;
            }
            float sp = sdp + 2.f * (dbxp * rbar.x + dbyp * rbar.y);
            float sn = sdn + 2.f * (dbxn * rbar.x + dbyn * rbar.y);
            diffpn = wsum(sp - sn);
        }
        // biases loaded late (short-lived)
        float biasP = __ldg(item_bias + cur.pid);
        float biasN = __ldg(item_bias + cur.nid);
        accSeq += nlsig((biasP - biasN) - diffpn);

        // ---- relation loss
        float prs = (cur.prid == 0) ? rw[0] : ((cur.prid == 1) ? rw[1] : rw[2]);
        float nrs = (cur.nrel == 0) ? rw[0] : ((cur.nrel == 1) ? rw[1] : rw[2]);
        accRel += nlsig(prs - nrs);

        // ---- item loss in one reduction
        float2 iir;
        iir.x = (cur.prid == 0) ? re[0].x : ((cur.prid == 1) ? re[1].x : re[2].x);
        iir.y = (cur.prid == 0) ? re[0].y : ((cur.prid == 1) ? re[1].y : re[2].y);
        float px = a.x + iir.x - p.x,   py = a.y + iir.y - p.y;
        float qx = a.x + iir.x - nri.x, qy = a.y + iir.y - nri.y;
        float di = wsum((px * px + py * py) - (qx * qx + qy * qy));
        float biasNR = __ldg(item_bias + cur.nrid);
        accItm += nlsig((biasP - biasNR) - di);

        // ---- rotate pipeline
        cur = nxt; cma = nma; cmp = nmp; cmn = nmn;
        b = nb;
    }

    // ---- deterministic block-level partial sum
    __shared__ float sh[WARPS_PER_BLOCK][3];
    __shared__ bool is_last;
    if (lane == 0) { sh[wid][0] = accSeq; sh[wid][1] = accRel; sh[wid][2] = accItm; }
    __syncthreads();
    if (threadIdx.x == 0) {
        float s0 = 0.f, s1 = 0.f, s2 = 0.f;
#pragma unroll
        for (int w = 0; w < WARPS_PER_BLOCK; w++) {
            s0 += sh[w][0]; s1 += sh[w][1]; s2 += sh[w][2];
        }
        g_partials[blockIdx.x * 3 + 0] = s0;
        g_partials[blockIdx.x * 3 + 1] = s1;
        g_partials[blockIdx.x * 3 + 2] = s2;
        __threadfence();
        unsigned int old = atomicAdd(&g_count, 1u);
        is_last = (old == gridDim.x - 1);
    }
    __syncthreads();

    // ---- last arriving block does the final (fixed-order, deterministic) reduce
    if (is_last) {
        const int nblocks = gridDim.x;
        __shared__ float shf[3];
        if (wid < 3) {
            float s = 0.f;
            for (int i = lane; i < nblocks; i += 32) s += g_partials[i * 3 + wid];
            s = wsum(s) * invB;
            if (lane == 0) shf[wid] = s;
        }
        __syncthreads();
        if (threadIdx.x == 0) {
            float seq = shf[0], rel = shf[1], itm = shf[2];
            out[0] = seq + rel + itm;   // loss (ALPHA=BETA=1)
            out[1] = rel;               // relation_loss
            out[2] = seq;               // seq_loss
            out[3] = itm;               // item_loss
            g_count = 0;                // reset for next graph replay
        }
    }
}

extern "C" void kernel_launch(void* const* d_in, const int* in_sizes, int n_in,
                              void* d_out, int out_size) {
    const int*   u_id       = (const int*)d_in[0];
    const int*   anchor_i   = (const int*)d_in[1];
    const int*   pos_r      = (const int*)d_in[2];
    const int*   pos_i      = (const int*)d_in[3];
    const int*   neg_r      = (const int*)d_in[4];
    const int*   neg_i      = (const int*)d_in[5];
    const int*   neg_ri     = (const int*)d_in[6];
    const int*   item_meta  = (const int*)d_in[7];
    const float* user_emb   = (const float*)d_in[8];
    const float* rel_emb    = (const float*)d_in[9];
    const float* item_emb   = (const float*)d_in[10];
    const float* item_emb_r = (const float*)d_in[11];
    const float* item_bias  = (const float*)d_in[12];
    const float* rel_bias   = (const float*)d_in[13];
    const float* meta_emb   = (const float*)d_in[14];
    const float* att_w_W    = (const float*)d_in[15];
    const float* att_v_W    = (const float*)d_in[17];

    const int B = in_sizes[0];

    precompute_w2<<<1, 64>>>(att_w_W, att_v_W);
    actr_main<<<GRID_BLOCKS, THREADS>>>(u_id, anchor_i, pos_r, pos_i, neg_r, neg_i, neg_ri,
                                        item_meta, user_emb, rel_emb, item_emb, item_emb_r,
                                        item_bias, rel_bias, meta_emb,
                                        (float*)d_out, B, 1.0f / (float)B);
}

// round 9
// speedup vs baseline: 1.3083x; 1.2000x over previous
#include <cuda_runtime.h>

#define WARPS_PER_BLOCK 4
#define THREADS 128
#define GRID_BLOCKS 512
#define MAX_BLOCKS 1024

__device__ __align__(16) float g_w2[64];
__device__ float g_partials[MAX_BLOCKS * 3];
__device__ unsigned int g_count = 0;

// 16-lane butterfly: both half-warps reduce independently (offsets < 16)
__device__ __forceinline__ float wsum16(float v) {
#pragma unroll
    for (int o = 8; o > 0; o >>= 1) v += __shfl_xor_sync(0xffffffffu, v, o);
    return v;
}

__device__ __forceinline__ float dot4(float4 a, float4 b) {
    return a.x * b.x + a.y * b.y + a.z * b.z + a.w * b.w;
}

// -log(sigmoid(x)) = softplus(-x); fast + stable (tol is 1e-3)
__device__ __forceinline__ float nlsig(float x) {
    float z = -x;
    return fmaxf(z, 0.f) + __logf(1.f + __expf(-fabsf(z)));
}

// w2[d] = sum_e att_w_W[d,e] * att_v_W[64+e]
__global__ void precompute_w2(const float* __restrict__ W, const float* __restrict__ vW) {
    const int d = threadIdx.x;
    const float4* Wr = (const float4*)(W + d * 64);
    const float4* vr = (const float4*)(vW + 64);
    float s = 0.f;
#pragma unroll
    for (int e = 0; e < 16; e++) {
        float4 w = __ldg(Wr + e);
        float4 v = __ldg(vr + e);
        s += w.x * v.x + w.y * v.y + w.z * v.z + w.w * v.w;
    }
    g_w2[d] = s;
}

struct Ids { int aid, pid, nid, uid, nrid, prid, nrel; };

__device__ __forceinline__ Ids load_ids(
    const int* __restrict__ u_id, const int* __restrict__ anchor_i_id,
    const int* __restrict__ pos_r_id, const int* __restrict__ pos_i_id,
    const int* __restrict__ neg_r_id, const int* __restrict__ neg_i_id,
    const int* __restrict__ neg_ri_id, int b)
{
    Ids s;
    s.aid  = __ldg(anchor_i_id + b);
    s.pid  = __ldg(pos_i_id + b);
    s.nid  = __ldg(neg_i_id + b);
    s.uid  = __ldg(u_id + b);
    s.nrid = __ldg(neg_ri_id + b);
    s.prid = __ldg(pos_r_id + b);
    s.nrel = __ldg(neg_r_id + b);
    return s;
}

__global__ void __launch_bounds__(THREADS, 4) actr_main(
    const int* __restrict__ u_id, const int* __restrict__ anchor_i_id,
    const int* __restrict__ pos_r_id, const int* __restrict__ pos_i_id,
    const int* __restrict__ neg_r_id, const int* __restrict__ neg_i_id,
    const int* __restrict__ neg_ri_id, const int* __restrict__ item_meta,
    const float* __restrict__ user_emb, const float* __restrict__ rel_emb,
    const float* __restrict__ item_emb, const float* __restrict__ item_emb_r,
    const float* __restrict__ item_bias, const float* __restrict__ rel_bias,
    const float* __restrict__ meta_emb,
    float* __restrict__ out, int B, float invB)
{
    const int lane = threadIdx.x & 31;
    const int half = lane >> 4;          // which sample of the pair
    const int hl   = lane & 15;          // lane within the 16-lane group
    const int wid  = threadIdx.x >> 5;
    const int S = gridDim.x * WARPS_PER_BLOCK * 2;   // samples per grid stride

    // ---- loop-invariant data: each lane holds dims [4*hl, 4*hl+3]
    float4 w2 = __ldg((const float4*)g_w2 + hl);
    float4 re[3];
#pragma unroll
    for (int r = 0; r < 3; r++)
        re[r] = __ldg((const float4*)rel_emb + r * 16 + hl);

    float accSeq = 0.f, accRel = 0.f, accItm = 0.f;

    int b = (blockIdx.x * WARPS_PER_BLOCK + wid) * 2 + half;
    const int Bm1 = B - 1;

    // ---- pipeline prologue: ids + meta indices for first sample
    Ids cur = load_ids(u_id, anchor_i_id, pos_r_id, pos_i_id, neg_r_id, neg_i_id, neg_ri_id,
                       min(b, Bm1));
    int4 cma = __ldg((const int4*)item_meta + cur.aid);
    int4 cmp = __ldg((const int4*)item_meta + cur.pid);
    int4 cmn = __ldg((const int4*)item_meta + cur.nid);

    while (b < B) {
        const int nb = b + S;

        // ---- issue ALL embedding gathers (indices already resolved); one
        // LDG.128 per lane; each half-warp covers its own sample's 256B row.
        float4 u   = __ldg((const float4*)user_emb   + (size_t)cur.uid  * 16 + hl);
        float4 ar  = __ldg((const float4*)item_emb_r + (size_t)cur.aid  * 16 + hl);
        float4 a   = __ldg((const float4*)item_emb   + (size_t)cur.aid  * 16 + hl);
        float4 p   = __ldg((const float4*)item_emb   + (size_t)cur.pid  * 16 + hl);
        float4 n   = __ldg((const float4*)item_emb   + (size_t)cur.nid  * 16 + hl);
        float4 nri = __ldg((const float4*)item_emb   + (size_t)cur.nrid * 16 + hl);

        const int mai[4] = {cma.x, cma.y, cma.z, cma.w};
        const int mpi[4] = {cmp.x, cmp.y, cmp.z, cmp.w};
        const int mni[4] = {cmn.x, cmn.y, cmn.z, cmn.w};
        float4 am[4], pm[4], nm[4];
#pragma unroll
        for (int g = 0; g < 4; g++) {
            am[g] = __ldg((const float4*)meta_emb + (size_t)mai[g] * 16 + hl);
            pm[g] = __ldg((const float4*)meta_emb + (size_t)mpi[g] * 16 + hl);
            nm[g] = __ldg((const float4*)meta_emb + (size_t)mni[g] * 16 + hl);
        }

        // ---- prefetch NEXT sample's ids (arrive during compute below)
        Ids nxt;
        if (nb < B)
            nxt = load_ids(u_id, anchor_i_id, pos_r_id, pos_i_id, neg_r_id, neg_i_id, neg_ri_id, nb);

        // ---- relation prediction: softmax_r( rel_bias[r] - ||u + a_r - rel_emb[r]||^2 )
        float4 uar;
        uar.x = u.x + ar.x; uar.y = u.y + ar.y; uar.z = u.z + ar.z; uar.w = u.w + ar.w;
        float rw[3];
#pragma unroll
        for (int r = 0; r < 3; r++) {
            float4 d;
            d.x = uar.x - re[r].x; d.y = uar.y - re[r].y;
            d.z = uar.z - re[r].z; d.w = uar.w - re[r].w;
            rw[r] = __ldg(rel_bias + r) - wsum16(dot4(d, d));
        }
        float mx = fmaxf(rw[0], fmaxf(rw[1], rw[2]));
        float ssum = 0.f;
#pragma unroll
        for (int r = 0; r < 3; r++) { rw[r] = __expf(rw[r] - mx); ssum += rw[r]; }
        float inv = __frcp_rn(ssum);
#pragma unroll
        for (int r = 0; r < 3; r++) rw[r] *= inv;

        // ---- attention coef: softmax_c( i_plus[c] . w2 )
        float cf[5];
        cf[0] = wsum16(dot4(a, w2));
#pragma unroll
        for (int g = 0; g < 4; g++)
            cf[1 + g] = wsum16(dot4(am[g], w2));
        mx = cf[0];
#pragma unroll
        for (int c = 1; c < 5; c++) mx = fmaxf(mx, cf[c]);
        ssum = 0.f;
#pragma unroll
        for (int c = 0; c < 5; c++) { cf[c] = __expf(cf[c] - mx); ssum += cf[c]; }
        inv = __frcp_rn(ssum);
#pragma unroll
        for (int c = 0; c < 5; c++) cf[c] *= inv;

        // ---- prefetch NEXT sample's meta indices (nxt ids have arrived by now)
        int4 nma, nmp, nmn;
        if (nb < B) {
            nma = __ldg((const int4*)item_meta + nxt.aid);
            nmp = __ldg((const int4*)item_meta + nxt.pid);
            nmn = __ldg((const int4*)item_meta + nxt.nid);
        }

        // ---- rbar = sum_r rel[r]*rue[r]  (||rue||^2 term cancels in pos-neg diff)
        const float GAMMA = 0.5f;
        float4 rbar;
        rbar.x = GAMMA * (rw[0] * re[0].x + rw[1] * re[1].x + rw[2] * re[2].x) + (1.f - GAMMA) * u.x;
        rbar.y = GAMMA * (rw[0] * re[0].y + rw[1] * re[1].y + rw[2] * re[2].y) + (1.f - GAMMA) * u.y;
        rbar.z = GAMMA * (rw[0] * re[0].z + rw[1] * re[1].z + rw[2] * re[2].z) + (1.f - GAMMA) * u.z;
        rbar.w = GAMMA * (rw[0] * re[0].w + rw[1] * re[1].w + rw[2] * re[2].w) + (1.f - GAMMA) * u.w;

        // ---- seq score difference in one reduction
        float diffpn;
        {
            float sdp = 0.f, sdn = 0.f;
            float4 dbp = make_float4(0.f, 0.f, 0.f, 0.f);
            float4 dbn = make_float4(0.f, 0.f, 0.f, 0.f);
            float4 d;
            d.x = a.x - p.x; d.y = a.y - p.y; d.z = a.z - p.z; d.w = a.w - p.w;
            sdp += cf[0] * dot4(d, d);
            dbp.x += cf[0] * d.x; dbp.y += cf[0] * d.y; dbp.z += cf[0] * d.z; dbp.w += cf[0] * d.w;
            d.x = a.x - n.x; d.y = a.y - n.y; d.z = a.z - n.z; d.w = a.w - n.w;
            sdn += cf[0] * dot4(d, d);
            dbn.x += cf[0] * d.x; dbn.y += cf[0] * d.y; dbn.z += cf[0] * d.z; dbn.w += cf[0] * d.w;
#pragma unroll
            for (int g = 0; g < 4; g++) {
                float c = cf[1 + g];
                d.x = am[g].x - pm[g].x; d.y = am[g].y - pm[g].y;
                d.z = am[g].z - pm[g].z; d.w = am[g].w - pm[g].w;
                sdp += c * dot4(d, d);
                dbp.x += c * d.x; dbp.y += c * d.y; dbp.z += c * d.z; dbp.w += c * d.w;
                d.x = am[g].x - nm[g].x; d.y = am[g].y - nm[g].y;
                d.z = am[g].z - nm[g].z; d.w = am[g].w - nm[g].w;
                sdn += c * dot4(d, d);
                dbn.x += c * d.x; dbn.y += c * d.y; dbn.z += c * d.z; dbn.w += c * d.w;
            }
            float sp = sdp + 2.f * dot4(dbp, rbar);
            float sn = sdn + 2.f * dot4(dbn, rbar);
            diffpn = wsum16(sp - sn);
        }
        float biasP = __ldg(item_bias + cur.pid);
        float biasN = __ldg(item_bias + cur.nid);

        // ---- item loss distance in one reduction
        float4 iir = (cur.prid == 0) ? re[0] : ((cur.prid == 1) ? re[1] : re[2]);
        float4 pv, qv;
        pv.x = a.x + iir.x - p.x;   pv.y = a.y + iir.y - p.y;
        pv.z = a.z + iir.z - p.z;   pv.w = a.w + iir.w - p.w;
        qv.x = a.x + iir.x - nri.x; qv.y = a.y + iir.y - nri.y;
        qv.z = a.z + iir.z - nri.z; qv.w = a.w + iir.w - nri.w;
        float di = wsum16(dot4(pv, pv) - dot4(qv, qv));
        float biasNR = __ldg(item_bias + cur.nrid);

        // ---- accumulate (b < B guaranteed by loop condition)
        accSeq += nlsig((biasP - biasN) - diffpn);
        float prs = (cur.prid == 0) ? rw[0] : ((cur.prid == 1) ? rw[1] : rw[2]);
        float nrs = (cur.nrel == 0) ? rw[0] : ((cur.nrel == 1) ? rw[1] : rw[2]);
        accRel += nlsig(prs - nrs);
        accItm += nlsig((biasP - biasNR) - di);

        // ---- rotate pipeline
        cur = nxt; cma = nma; cmp = nmp; cmn = nmn;
        b = nb;
    }

    // ---- combine the two half-warp accumulators (deterministic order)
    accSeq += __shfl_xor_sync(0xffffffffu, accSeq, 16);
    accRel += __shfl_xor_sync(0xffffffffu, accRel, 16);
    accItm += __shfl_xor_sync(0xffffffffu, accItm, 16);

    // ---- deterministic block-level partial sum
    __shared__ float sh[WARPS_PER_BLOCK][3];
    __shared__ bool is_last;
    if (lane == 0) { sh[wid][0] = accSeq; sh[wid][1] = accRel; sh[wid][2] = accItm; }
    __syncthreads();
    if (threadIdx.x == 0) {
        float s0 = 0.f, s1 = 0.f, s2 = 0.f;
#pragma unroll
        for (int w = 0; w < WARPS_PER_BLOCK; w++) {
            s0 += sh[w][0]; s1 += sh[w][1]; s2 += sh[w][2];
        }
        g_partials[blockIdx.x * 3 + 0] = s0;
        g_partials[blockIdx.x * 3 + 1] = s1;
        g_partials[blockIdx.x * 3 + 2] = s2;
        __threadfence();
        unsigned int old = atomicAdd(&g_count, 1u);
        is_last = (old == gridDim.x - 1);
    }
    __syncthreads();

    // ---- last arriving block does the final (fixed-order, deterministic) reduce
    if (is_last) {
        const int nblocks = gridDim.x;
        __shared__ float shf[3];
        if (wid < 3) {
            float s = 0.f;
            for (int i = lane; i < nblocks; i += 32) s += g_partials[i * 3 + wid];
#pragma unroll
            for (int o = 16; o > 0; o >>= 1) s += __shfl_xor_sync(0xffffffffu, s, o);
            s *= invB;
            if (lane == 0) shf[wid] = s;
        }
        __syncthreads();
        if (threadIdx.x == 0) {
            float seq = shf[0], rel = shf[1], itm = shf[2];
            out[0] = seq + rel + itm;   // loss (ALPHA=BETA=1)
            out[1] = rel;               // relation_loss
            out[2] = seq;               // seq_loss
            out[3] = itm;               // item_loss
            g_count = 0;                // reset for next graph replay
        }
    }
}

extern "C" void kernel_launch(void* const* d_in, const int* in_sizes, int n_in,
                              void* d_out, int out_size) {
    const int*   u_id       = (const int*)d_in[0];
    const int*   anchor_i   = (const int*)d_in[1];
    const int*   pos_r      = (const int*)d_in[2];
    const int*   pos_i      = (const int*)d_in[3];
    const int*   neg_r      = (const int*)d_in[4];
    const int*   neg_i      = (const int*)d_in[5];
    const int*   neg_ri     = (const int*)d_in[6];
    const int*   item_meta  = (const int*)d_in[7];
    const float* user_emb   = (const float*)d_in[8];
    const float* rel_emb    = (const float*)d_in[9];
    const float* item_emb   = (const float*)d_in[10];
    const float* item_emb_r = (const float*)d_in[11];
    const float* item_bias  = (const float*)d_in[12];
    const float* rel_bias   = (const float*)d_in[13];
    const float* meta_emb   = (const float*)d_in[14];
    const float* att_w_W    = (const float*)d_in[15];
    const float* att_v_W    = (const float*)d_in[17];

    const int B = in_sizes[0];

    precompute_w2<<<1, 64>>>(att_w_W, att_v_W);
    actr_main<<<GRID_BLOCKS, THREADS>>>(u_id, anchor_i, pos_r, pos_i, neg_r, neg_i, neg_ri,
                                        item_meta, user_emb, rel_emb, item_emb, item_emb_r,
                                        item_bias, rel_bias, meta_emb,
                                        (float*)d_out, B, 1.0f / (float)B);
}

// round 10
// speedup vs baseline: 1.3260x; 1.0135x over previous
#include <cuda_runtime.h>

#define WARPS_PER_BLOCK 4
#define THREADS 128
#define GRID_BLOCKS 512
#define MAX_BLOCKS 1024

__device__ __align__(16) float g_w2[64];
__device__ float g_partials[MAX_BLOCKS * 3];
__device__ unsigned int g_count = 0;

// 16-lane butterfly: both half-warps reduce independently (offsets < 16)
__device__ __forceinline__ float wsum16(float v) {
#pragma unroll
    for (int o = 8; o > 0; o >>= 1) v += __shfl_xor_sync(0xffffffffu, v, o);
    return v;
}

__device__ __forceinline__ float dot4(float4 a, float4 b) {
    return a.x * b.x + a.y * b.y + a.z * b.z + a.w * b.w;
}

// -log(sigmoid(x)) = softplus(-x); fast + stable (tol is 1e-3)
__device__ __forceinline__ float nlsig(float x) {
    float z = -x;
    return fmaxf(z, 0.f) + __logf(1.f + __expf(-fabsf(z)));
}

// L2 prefetch, no destination register, no scoreboard
__device__ __forceinline__ void pf_l2(const void* p) {
    asm volatile("prefetch.global.L2 [%0];" :: "l"(p));
}

// w2[d] = sum_e att_w_W[d,e] * att_v_W[64+e]
__global__ void precompute_w2(const float* __restrict__ W, const float* __restrict__ vW) {
    const int d = threadIdx.x;
    const float4* Wr = (const float4*)(W + d * 64);
    const float4* vr = (const float4*)(vW + 64);
    float s = 0.f;
#pragma unroll
    for (int e = 0; e < 16; e++) {
        float4 w = __ldg(Wr + e);
        float4 v = __ldg(vr + e);
        s += w.x * v.x + w.y * v.y + w.z * v.z + w.w * v.w;
    }
    g_w2[d] = s;
}

struct Ids { int aid, pid, nid, uid, nrid, prid, nrel; };

__device__ __forceinline__ Ids load_ids(
    const int* __restrict__ u_id, const int* __restrict__ anchor_i_id,
    const int* __restrict__ pos_r_id, const int* __restrict__ pos_i_id,
    const int* __restrict__ neg_r_id, const int* __restrict__ neg_i_id,
    const int* __restrict__ neg_ri_id, int b)
{
    Ids s;
    s.aid  = __ldg(anchor_i_id + b);
    s.pid  = __ldg(pos_i_id + b);
    s.nid  = __ldg(neg_i_id + b);
    s.uid  = __ldg(u_id + b);
    s.nrid = __ldg(neg_ri_id + b);
    s.prid = __ldg(pos_r_id + b);
    s.nrel = __ldg(neg_r_id + b);
    return s;
}

__global__ void __launch_bounds__(THREADS, 4) actr_main(
    const int* __restrict__ u_id, const int* __restrict__ anchor_i_id,
    const int* __restrict__ pos_r_id, const int* __restrict__ pos_i_id,
    const int* __restrict__ neg_r_id, const int* __restrict__ neg_i_id,
    const int* __restrict__ neg_ri_id, const int* __restrict__ item_meta,
    const float* __restrict__ user_emb, const float* __restrict__ rel_emb,
    const float* __restrict__ item_emb, const float* __restrict__ item_emb_r,
    const float* __restrict__ item_bias, const float* __restrict__ rel_bias,
    const float* __restrict__ meta_emb,
    float* __restrict__ out, int B, float invB)
{
    const int lane = threadIdx.x & 31;
    const int half = lane >> 4;          // which sample of the pair
    const int hl   = lane & 15;          // lane within the 16-lane group
    const int wid  = threadIdx.x >> 5;
    const int S = gridDim.x * WARPS_PER_BLOCK * 2;   // samples per grid stride
    const bool pfl = ((hl & 7) == 0);    // 2 lanes per 256B row -> both 128B lines

    // ---- loop-invariant data: each lane holds dims [4*hl, 4*hl+3]
    float4 w2 = __ldg((const float4*)g_w2 + hl);
    float4 re[3];
    float relb[3];
#pragma unroll
    for (int r = 0; r < 3; r++) {
        re[r] = __ldg((const float4*)rel_emb + r * 16 + hl);
        relb[r] = __ldg(rel_bias + r);
    }

    float accSeq = 0.f, accRel = 0.f, accItm = 0.f;

    int b = (blockIdx.x * WARPS_PER_BLOCK + wid) * 2 + half;
    const int Bm1 = B - 1;

    // ---- pipeline prologue: ids + meta indices for first sample
    Ids cur = load_ids(u_id, anchor_i_id, pos_r_id, pos_i_id, neg_r_id, neg_i_id, neg_ri_id,
                       min(b, Bm1));
    int4 cma = __ldg((const int4*)item_meta + cur.aid);
    int4 cmp = __ldg((const int4*)item_meta + cur.pid);
    int4 cmn = __ldg((const int4*)item_meta + cur.nid);

    while (b < B) {
        const int nb = b + S;

        // ---- issue ALL embedding gathers (indices resolved + L2-prefetched last iter)
        float4 u   = __ldg((const float4*)user_emb   + (size_t)cur.uid  * 16 + hl);
        float4 ar  = __ldg((const float4*)item_emb_r + (size_t)cur.aid  * 16 + hl);
        float4 a   = __ldg((const float4*)item_emb   + (size_t)cur.aid  * 16 + hl);
        float4 p   = __ldg((const float4*)item_emb   + (size_t)cur.pid  * 16 + hl);
        float4 n   = __ldg((const float4*)item_emb   + (size_t)cur.nid  * 16 + hl);
        float4 nri = __ldg((const float4*)item_emb   + (size_t)cur.nrid * 16 + hl);

        const int mai[4] = {cma.x, cma.y, cma.z, cma.w};
        const int mpi[4] = {cmp.x, cmp.y, cmp.z, cmp.w};
        const int mni[4] = {cmn.x, cmn.y, cmn.z, cmn.w};
        float4 am[4], pm[4], nm[4];
#pragma unroll
        for (int g = 0; g < 4; g++) {
            am[g] = __ldg((const float4*)meta_emb + (size_t)mai[g] * 16 + hl);
            pm[g] = __ldg((const float4*)meta_emb + (size_t)mpi[g] * 16 + hl);
            nm[g] = __ldg((const float4*)meta_emb + (size_t)mni[g] * 16 + hl);
        }

        // ---- prefetch NEXT sample's ids (arrive during compute below)
        Ids nxt;
        if (nb < B)
            nxt = load_ids(u_id, anchor_i_id, pos_r_id, pos_i_id, neg_r_id, neg_i_id, neg_ri_id, nb);

        // ---- relation prediction: softmax_r( rel_bias[r] - ||u + a_r - rel_emb[r]||^2 )
        float4 uar;
        uar.x = u.x + ar.x; uar.y = u.y + ar.y; uar.z = u.z + ar.z; uar.w = u.w + ar.w;
        float rw[3];
#pragma unroll
        for (int r = 0; r < 3; r++) {
            float4 d;
            d.x = uar.x - re[r].x; d.y = uar.y - re[r].y;
            d.z = uar.z - re[r].z; d.w = uar.w - re[r].w;
            rw[r] = relb[r] - wsum16(dot4(d, d));
        }
        float mx = fmaxf(rw[0], fmaxf(rw[1], rw[2]));
        float ssum = 0.f;
#pragma unroll
        for (int r = 0; r < 3; r++) { rw[r] = __expf(rw[r] - mx); ssum += rw[r]; }
        float inv = __frcp_rn(ssum);
#pragma unroll
        for (int r = 0; r < 3; r++) rw[r] *= inv;

        // ---- attention coef: softmax_c( i_plus[c] . w2 )
        float cf[5];
        cf[0] = wsum16(dot4(a, w2));
#pragma unroll
        for (int g = 0; g < 4; g++)
            cf[1 + g] = wsum16(dot4(am[g], w2));
        mx = cf[0];
#pragma unroll
        for (int c = 1; c < 5; c++) mx = fmaxf(mx, cf[c]);
        ssum = 0.f;
#pragma unroll
        for (int c = 0; c < 5; c++) { cf[c] = __expf(cf[c] - mx); ssum += cf[c]; }
        inv = __frcp_rn(ssum);
#pragma unroll
        for (int c = 0; c < 5; c++) cf[c] *= inv;

        // ---- next-sample L2 prefetch: user/item rows (ids arrived; no reg cost)
        if (nb < B && pfl) {
            const float* base = (const float*)((const float4*)user_emb + (size_t)nxt.uid * 16 + hl);
            pf_l2(base);
            pf_l2((const float4*)item_emb_r + (size_t)nxt.aid  * 16 + hl);
            pf_l2((const float4*)item_emb   + (size_t)nxt.aid  * 16 + hl);
            pf_l2((const float4*)item_emb   + (size_t)nxt.pid  * 16 + hl);
            pf_l2((const float4*)item_emb   + (size_t)nxt.nid  * 16 + hl);
            pf_l2((const float4*)item_emb   + (size_t)nxt.nrid * 16 + hl);
        }

        // ---- prefetch NEXT sample's meta indices (nxt ids have arrived by now)
        int4 nma, nmp, nmn;
        if (nb < B) {
            nma = __ldg((const int4*)item_meta + nxt.aid);
            nmp = __ldg((const int4*)item_meta + nxt.pid);
            nmn = __ldg((const int4*)item_meta + nxt.nid);
        }

        // ---- rbar = sum_r rel[r]*rue[r]  (||rue||^2 term cancels in pos-neg diff)
        const float GAMMA = 0.5f;
        float4 rbar;
        rbar.x = GAMMA * (rw[0] * re[0].x + rw[1] * re[1].x + rw[2] * re[2].x) + (1.f - GAMMA) * u.x;
        rbar.y = GAMMA * (rw[0] * re[0].y + rw[1] * re[1].y + rw[2] * re[2].y) + (1.f - GAMMA) * u.y;
        rbar.z = GAMMA * (rw[0] * re[0].z + rw[1] * re[1].z + rw[2] * re[2].z) + (1.f - GAMMA) * u.z;
        rbar.w = GAMMA * (rw[0] * re[0].w + rw[1] * re[1].w + rw[2] * re[2].w) + (1.f - GAMMA) * u.w;

        // ---- seq score difference in one reduction
        float diffpn;
        {
            float sdp = 0.f, sdn = 0.f;
            float4 dbp = make_float4(0.f, 0.f, 0.f, 0.f);
            float4 dbn = make_float4(0.f, 0.f, 0.f, 0.f);
            float4 d;
            d.x = a.x - p.x; d.y = a.y - p.y; d.z = a.z - p.z; d.w = a.w - p.w;
            sdp += cf[0] * dot4(d, d);
            dbp.x += cf[0] * d.x; dbp.y += cf[0] * d.y; dbp.z += cf[0] * d.z; dbp.w += cf[0] * d.w;
            d.x = a.x - n.x; d.y = a.y - n.y; d.z = a.z - n.z; d.w = a.w - n.w;
            sdn += cf[0] * dot4(d, d);
            dbn.x += cf[0] * d.x; dbn.y += cf[0] * d.y; dbn.z += cf[0] * d.z; dbn.w += cf[0] * d.w;
#pragma unroll
            for (int g = 0; g < 4; g++) {
                float c = cf[1 + g];
                d.x = am[g].x - pm[g].x; d.y = am[g].y - pm[g].y;
                d.z = am[g].z - pm[g].z; d.w = am[g].w - pm[g].w;
                sdp += c * dot4(d, d);
                dbp.x += c * d.x; dbp.y += c * d.y; dbp.z += c * d.z; dbp.w += c * d.w;
                d.x = am[g].x - nm[g].x; d.y = am[g].y - nm[g].y;
                d.z = am[g].z - nm[g].z; d.w = am[g].w - nm[g].w;
                sdn += c * dot4(d, d);
                dbn.x += c * d.x; dbn.y += c * d.y; dbn.z += c * d.z; dbn.w += c * d.w;
            }
            float sp = sdp + 2.f * dot4(dbp, rbar);
            float sn = sdn + 2.f * dot4(dbn, rbar);
            diffpn = wsum16(sp - sn);
        }
        float biasP = __ldg(item_bias + cur.pid);
        float biasN = __ldg(item_bias + cur.nid);

        // ---- next-sample L2 prefetch: meta rows (meta indices just arrived)
        if (nb < B && pfl) {
            pf_l2((const float4*)meta_emb + (size_t)nma.x * 16 + hl);
            pf_l2((const float4*)meta_emb + (size_t)nma.y * 16 + hl);
            pf_l2((const float4*)meta_emb + (size_t)nma.z * 16 + hl);
            pf_l2((const float4*)meta_emb + (size_t)nma.w * 16 + hl);
            pf_l2((const float4*)meta_emb + (size_t)nmp.x * 16 + hl);
            pf_l2((const float4*)meta_emb + (size_t)nmp.y * 16 + hl);
            pf_l2((const float4*)meta_emb + (size_t)nmp.z * 16 + hl);
            pf_l2((const float4*)meta_emb + (size_t)nmp.w * 16 + hl);
            pf_l2((const float4*)meta_emb + (size_t)nmn.x * 16 + hl);
            pf_l2((const float4*)meta_emb + (size_t)nmn.y * 16 + hl);
            pf_l2((const float4*)meta_emb + (size_t)nmn.z * 16 + hl);
            pf_l2((const float4*)meta_emb + (size_t)nmn.w * 16 + hl);
        }

        // ---- item loss distance in one reduction
        float4 iir = (cur.prid == 0) ? re[0] : ((cur.prid == 1) ? re[1] : re[2]);
        float4 pv, qv;
        pv.x = a.x + iir.x - p.x;   pv.y = a.y + iir.y - p.y;
        pv.z = a.z + iir.z - p.z;   pv.w = a.w + iir.w - p.w;
        qv.x = a.x + iir.x - nri.x; qv.y = a.y + iir.y - nri.y;
        qv.z = a.z + iir.z - nri.z; qv.w = a.w + iir.w - nri.w;
        float di = wsum16(dot4(pv, pv) - dot4(qv, qv));
        float biasNR = __ldg(item_bias + cur.nrid);

        // ---- accumulate (b < B guaranteed by loop condition)
        accSeq += nlsig((biasP - biasN) - diffpn);
        float prs = (cur.prid == 0) ? rw[0] : ((cur.prid == 1) ? rw[1] : rw[2]);
        float nrs = (cur.nrel == 0) ? rw[0] : ((cur.nrel == 1) ? rw[1] : rw[2]);
        accRel += nlsig(prs - nrs);
        accItm += nlsig((biasP - biasNR) - di);

        // ---- rotate pipeline
        cur = nxt; cma = nma; cmp = nmp; cmn = nmn;
        b = nb;
    }

    // ---- combine the two half-warp accumulators (deterministic order)
    accSeq += __shfl_xor_sync(0xffffffffu, accSeq, 16);
    accRel += __shfl_xor_sync(0xffffffffu, accRel, 16);
    accItm += __shfl_xor_sync(0xffffffffu, accItm, 16);

    // ---- deterministic block-level partial sum
    __shared__ float sh[WARPS_PER_BLOCK][3];
    __shared__ bool is_last;
    if (lane == 0) { sh[wid][0] = accSeq; sh[wid][1] = accRel; sh[wid][2] = accItm; }
    __syncthreads();
    if (threadIdx.x == 0) {
        float s0 = 0.f, s1 = 0.f, s2 = 0.f;
#pragma unroll
        for (int w = 0; w < WARPS_PER_BLOCK; w++) {
            s0 += sh[w][0]; s1 += sh[w][1]; s2 += sh[w][2];
        }
        g_partials[blockIdx.x * 3 + 0] = s0;
        g_partials[blockIdx.x * 3 + 1] = s1;
        g_partials[blockIdx.x * 3 + 2] = s2;
        __threadfence();
        unsigned int old = atomicAdd(&g_count, 1u);
        is_last = (old == gridDim.x - 1);
    }
    __syncthreads();

    // ---- last arriving block does the final (fixed-order, deterministic) reduce
    if (is_last) {
        const int nblocks = gridDim.x;
        __shared__ float shf[3];
        if (wid < 3) {
            float s = 0.f;
            for (int i = lane; i < nblocks; i += 32) s += g_partials[i * 3 + wid];
#pragma unroll
            for (int o = 16; o > 0; o >>= 1) s += __shfl_xor_sync(0xffffffffu, s, o);
            s *= invB;
            if (lane == 0) shf[wid] = s;
        }
        __syncthreads();
        if (threadIdx.x == 0) {
            float seq = shf[0], rel = shf[1], itm = shf[2];
            out[0] = seq + rel + itm;   // loss (ALPHA=BETA=1)
            out[1] = rel;               // relation_loss
            out[2] = seq;               // seq_loss
            out[3] = itm;               // item_loss
            g_count = 0;                // reset for next graph replay
        }
    }
}

extern "C" void kernel_launch(void* const* d_in, const int* in_sizes, int n_in,
                              void* d_out, int out_size) {
    const int*   u_id       = (const int*)d_in[0];
    const int*   anchor_i   = (const int*)d_in[1];
    const int*   pos_r      = (const int*)d_in[2];
    const int*   pos_i      = (const int*)d_in[3];
    const int*   neg_r      = (const int*)d_in[4];
    const int*   neg_i      = (const int*)d_in[5];
    const int*   neg_ri     = (const int*)d_in[6];
    const int*   item_meta  = (const int*)d_in[7];
    const float* user_emb   = (const float*)d_in[8];
    const float* rel_emb    = (const float*)d_in[9];
    const float* item_emb   = (const float*)d_in[10];
    const float* item_emb_r = (const float*)d_in[11];
    const float* item_bias  = (const float*)d_in[12];
    const float* rel_bias   = (const float*)d_in[13];
    const float* meta_emb   = (const float*)d_in[14];
    const float* att_w_W    = (const float*)d_in[15];
    const float* att_v_W    = (const float*)d_in[17];

    const int B = in_sizes[0];

    precompute_w2<<<1, 64>>>(att_w_W, att_v_W);
    actr_main<<<GRID_BLOCKS, THREADS>>>(u_id, anchor_i, pos_r, pos_i, neg_r, neg_i, neg_ri,
                                        item_meta, user_emb, rel_emb, item_emb, item_emb_r,
                                        item_bias, rel_bias, meta_emb,
                                        (float*)d_out, B, 1.0f / (float)B);
}